// round 1
// baseline (speedup 1.0000x reference)
#include <cuda_runtime.h>
#include <cuda_bf16.h>
#include <cstdint>

#define BDIM   1024
#define BATCH  32
#define SEQ    2048
#define MROWS  (BATCH * SEQ)

#define BM 128
#define BN 128
#define BK 32
#define STRIDE 36                 // floats per smem row (pad: conflict-free frags)
#define KTILES (BDIM / BK)        // 32
#define NTILES (BDIM / BN)        // 8
#define SMEM_FLOATS (4 * 128 * STRIDE + 128)
#define SMEM_BYTES  (SMEM_FLOATS * 4)

__device__ float g_logits[MROWS];

__device__ __forceinline__ uint32_t cvt_tf32(float x) {
    uint32_t r;
    asm("cvt.rna.tf32.f32 %0, %1;" : "=r"(r) : "f"(x));
    return r;
}

__device__ __forceinline__ float fast_tanh(float x) {
    // tanh(x) = 1 - 2/(exp(2x)+1). ex2.approx + rcp-based fast divide: ~1e-6 err.
    float e = __expf(2.0f * x);
    return 1.0f - __fdividef(2.0f, e + 1.0f);
}

__device__ __forceinline__ uint32_t smem_u32(const void* p) {
    return (uint32_t)__cvta_generic_to_shared(p);
}

__device__ __forceinline__ void cp_async16(uint32_t saddr, const void* gaddr) {
    asm volatile("cp.async.cg.shared.global [%0], [%1], 16;\n" :: "r"(saddr), "l"(gaddr));
}

// ---------------------------------------------------------------------------
// Kernel A: logits[m] = sum_e v[e] * tanh( sum_d X[m,d] * W[e,d] )
// tf32 mma.sync GEMM, fused tanh + v-dot epilogue. One CTA per 128-row M tile.
// ---------------------------------------------------------------------------
__global__ __launch_bounds__(256, 2)
void logits_kernel(const float* __restrict__ X, const float* __restrict__ W,
                   const float* __restrict__ v) {
    extern __shared__ float smem[];
    float* As0 = smem;
    float* Bs0 = smem + 128 * STRIDE;
    float* As1 = smem + 2 * 128 * STRIDE;
    float* Bs1 = smem + 3 * 128 * STRIDE;
    float* rowsum = smem + 4 * 128 * STRIDE;

    const int tid  = threadIdx.x;
    const int warp = tid >> 5;
    const int lane = tid & 31;
    const int wm = warp >> 1;          // 0..3  (32-row groups)
    const int wn = warp & 1;           // 0..1  (64-col groups)
    const int l4 = lane & 3;
    const int lg = lane >> 2;

    const int m0 = blockIdx.x * BM;

    if (tid < 128) rowsum[tid] = 0.0f;

    // tile-loader indexing: each thread loads 4 float4 per tile
    const int lr = tid >> 3;           // 0..31
    const int lc = (tid & 7) * 4;      // float col offset (16B aligned)

    float part[4] = {0.f, 0.f, 0.f, 0.f};

    for (int nt = 0; nt < NTILES; ++nt) {
        const float* Bbase = W + (size_t)(nt * BN) * BDIM;

        float acc[2][8][4];
        #pragma unroll
        for (int i = 0; i < 2; ++i)
            #pragma unroll
            for (int j = 0; j < 8; ++j)
                #pragma unroll
                for (int q = 0; q < 4; ++q) acc[i][j][q] = 0.0f;

        // prefetch k-tile 0 into buffer 0
        #pragma unroll
        for (int i = 0; i < 4; ++i) {
            int r = lr + 32 * i;
            cp_async16(smem_u32(&As0[r * STRIDE + lc]),
                       X + (size_t)(m0 + r) * BDIM + lc);
            cp_async16(smem_u32(&Bs0[r * STRIDE + lc]),
                       Bbase + (size_t)r * BDIM + lc);
        }
        asm volatile("cp.async.commit_group;\n");

        for (int kt = 0; kt < KTILES; ++kt) {
            asm volatile("cp.async.wait_group 0;\n");
            __syncthreads();

            const float* A = (kt & 1) ? As1 : As0;
            const float* B = (kt & 1) ? Bs1 : Bs0;

            if (kt + 1 < KTILES) {
                float* An = (kt & 1) ? As0 : As1;
                float* Bn = (kt & 1) ? Bs0 : Bs1;
                const int kof = (kt + 1) * BK;
                #pragma unroll
                for (int i = 0; i < 4; ++i) {
                    int r = lr + 32 * i;
                    cp_async16(smem_u32(&An[r * STRIDE + lc]),
                               X + (size_t)(m0 + r) * BDIM + kof + lc);
                    cp_async16(smem_u32(&Bn[r * STRIDE + lc]),
                               Bbase + (size_t)r * BDIM + kof + lc);
                }
                asm volatile("cp.async.commit_group;\n");
            }

            #pragma unroll
            for (int kk = 0; kk < 4; ++kk) {
                const int kc = kk * 8 + l4;
                uint32_t bf[8][2];
                #pragma unroll
                for (int j = 0; j < 8; ++j) {
                    int n = wn * 64 + j * 8 + lg;
                    bf[j][0] = cvt_tf32(B[n * STRIDE + kc]);
                    bf[j][1] = cvt_tf32(B[n * STRIDE + kc + 4]);
                }
                #pragma unroll
                for (int mi = 0; mi < 2; ++mi) {
                    int r = wm * 32 + mi * 16 + lg;
                    uint32_t a0 = cvt_tf32(A[r * STRIDE + kc]);
                    uint32_t a1 = cvt_tf32(A[(r + 8) * STRIDE + kc]);
                    uint32_t a2 = cvt_tf32(A[r * STRIDE + kc + 4]);
                    uint32_t a3 = cvt_tf32(A[(r + 8) * STRIDE + kc + 4]);
                    #pragma unroll
                    for (int j = 0; j < 8; ++j) {
                        asm volatile(
                            "mma.sync.aligned.m16n8k8.row.col.f32.tf32.tf32.f32 "
                            "{%0,%1,%2,%3}, {%4,%5,%6,%7}, {%8,%9}, {%0,%1,%2,%3};\n"
                            : "+f"(acc[mi][j][0]), "+f"(acc[mi][j][1]),
                              "+f"(acc[mi][j][2]), "+f"(acc[mi][j][3])
                            : "r"(a0), "r"(a1), "r"(a2), "r"(a3),
                              "r"(bf[j][0]), "r"(bf[j][1]));
                    }
                }
            }
            __syncthreads();
        }

        // fused epilogue for this n-tile: tanh then dot with v, per-row partials
        #pragma unroll
        for (int mi = 0; mi < 2; ++mi) {
            #pragma unroll
            for (int j = 0; j < 8; ++j) {
                int c = nt * BN + wn * 64 + j * 8 + l4 * 2;
                float v0 = __ldg(&v[c]);
                float v1 = __ldg(&v[c + 1]);
                part[mi * 2 + 0] += v0 * fast_tanh(acc[mi][j][0])
                                  + v1 * fast_tanh(acc[mi][j][1]);
                part[mi * 2 + 1] += v0 * fast_tanh(acc[mi][j][2])
                                  + v1 * fast_tanh(acc[mi][j][3]);
            }
        }
    }

    // reduce the 4 lanes that share each row (same lg, l4 = 0..3)
    #pragma unroll
    for (int p = 0; p < 4; ++p) {
        part[p] += __shfl_xor_sync(0xffffffffu, part[p], 1);
        part[p] += __shfl_xor_sync(0xffffffffu, part[p], 2);
    }
    if (l4 == 0) {
        int rbase = wm * 32 + lg;
        atomicAdd(&rowsum[rbase + 0],  part[0]);
        atomicAdd(&rowsum[rbase + 8],  part[1]);
        atomicAdd(&rowsum[rbase + 16], part[2]);
        atomicAdd(&rowsum[rbase + 24], part[3]);
    }
    __syncthreads();
    if (tid < 128) g_logits[m0 + tid] = rowsum[tid];
}

// ---------------------------------------------------------------------------
// Kernel B: softmax over S=2048 per batch. Also zero-fills the weighted-
// context region of d_out (bias b omitted: softmax is shift-invariant).
// ---------------------------------------------------------------------------
__global__ void softmax_kernel(float* __restrict__ out) {
    __shared__ float red[8];
    const int b = blockIdx.x;
    const int tid = threadIdx.x;
    const int warp = tid >> 5, lane = tid & 31;
    const float* lp = g_logits + b * SEQ;

    float vals[8];
    float m = -1e30f;
    #pragma unroll
    for (int i = 0; i < 8; ++i) {
        vals[i] = lp[i * 256 + tid];
        m = fmaxf(m, vals[i]);
    }
    #pragma unroll
    for (int o = 16; o > 0; o >>= 1) m = fmaxf(m, __shfl_xor_sync(~0u, m, o));
    if (lane == 0) red[warp] = m;
    __syncthreads();
    float bm = red[0];
    #pragma unroll
    for (int w = 1; w < 8; ++w) bm = fmaxf(bm, red[w]);
    __syncthreads();

    float s = 0.0f;
    #pragma unroll
    for (int i = 0; i < 8; ++i) {
        vals[i] = __expf(vals[i] - bm);
        s += vals[i];
    }
    #pragma unroll
    for (int o = 16; o > 0; o >>= 1) s += __shfl_xor_sync(~0u, s, o);
    if (lane == 0) red[warp] = s;
    __syncthreads();
    float ts = 0.0f;
    #pragma unroll
    for (int w = 0; w < 8; ++w) ts += red[w];

    float inv = 1.0f / ts;
    #pragma unroll
    for (int i = 0; i < 8; ++i)
        out[BATCH * BDIM + b * SEQ + i * 256 + tid] = vals[i] * inv;

    // zero weighted-context region (accumulated atomically by kernel C)
    for (int d = tid; d < BDIM; d += 256) out[b * BDIM + d] = 0.0f;
}

// ---------------------------------------------------------------------------
// Kernel C: weighted_context[b,d] = sum_s attn[b,s] * X[b,s,d]
// grid (4 d-chunks, 4 s-chunks, 32 batches); memory bound.
// ---------------------------------------------------------------------------
__global__ void weighted_kernel(const float* __restrict__ X, float* __restrict__ out) {
    const int d  = blockIdx.x * 256 + threadIdx.x;
    const int b  = blockIdx.z;
    const int s0 = blockIdx.y * 512;
    const float* attn = out + BATCH * BDIM + b * SEQ;
    const float* xb = X + ((size_t)b * SEQ + s0) * BDIM + d;

    float a0 = 0.f, a1 = 0.f, a2 = 0.f, a3 = 0.f;
    for (int s = 0; s < 512; s += 4) {
        a0 += attn[s0 + s + 0] * xb[(size_t)(s + 0) * BDIM];
        a1 += attn[s0 + s + 1] * xb[(size_t)(s + 1) * BDIM];
        a2 += attn[s0 + s + 2] * xb[(size_t)(s + 2) * BDIM];
        a3 += attn[s0 + s + 3] * xb[(size_t)(s + 3) * BDIM];
    }
    atomicAdd(&out[b * BDIM + d], (a0 + a1) + (a2 + a3));
}

// ---------------------------------------------------------------------------
extern "C" void kernel_launch(void* const* d_in, const int* in_sizes, int n_in,
                              void* d_out, int out_size) {
    const float* X = (const float*)d_in[0];   // context [32,2048,1024]
    const float* W = (const float*)d_in[1];   // [1024,1024]
    const float* v = (const float*)d_in[2];   // [1024]
    // d_in[3] = b: irrelevant (softmax shift invariance)
    float* out = (float*)d_out;               // [wc 32*1024 | attn 32*2048]

    cudaFuncSetAttribute(logits_kernel,
                         cudaFuncAttributeMaxDynamicSharedMemorySize, SMEM_BYTES);

    logits_kernel<<<MROWS / BM, 256, SMEM_BYTES>>>(X, W, v);
    softmax_kernel<<<BATCH, 256>>>(out);
    weighted_kernel<<<dim3(4, 4, BATCH), 256>>>(X, out);
}